// round 11
// baseline (speedup 1.0000x reference)
#include <cuda_runtime.h>
#include <cuda_bf16.h>
#include <math.h>
#include <stdint.h>

#define NN 4096
#define DD 128
#define C_ALPHA 10.0f
#define C_BETA  2.0f
#define C_BASE  0.7f
#define C_EPS   1e-6f
#define TILE_B 32768

// ---------------- device scratch ----------------
__device__ __nv_bfloat16 g_xhi[(size_t)NN * DD];   // 1 MB
__device__ __nv_bfloat16 g_xlo[(size_t)NN * DD];   // 1 MB
__device__ float g_sim[(size_t)NN * NN];           // 64 MB
__device__ float g_rowpart[NN * 4];
__device__ float g_rowap[NN];
__device__ float g_last[4];
__device__ int   g_ctr;

// ---------------- helpers ----------------
__device__ __forceinline__ uint32_t smem_u32(const void* p) {
    uint32_t a;
    asm("{ .reg .u64 t; cvta.to.shared.u64 t, %1; cvt.u32.u64 %0, t; }" : "=r"(a) : "l"(p));
    return a;
}
__device__ __forceinline__ void ldsm_x4(uint32_t& r0, uint32_t& r1, uint32_t& r2, uint32_t& r3,
                                        uint32_t addr) {
    asm volatile("ldmatrix.sync.aligned.m8n8.x4.shared.b16 {%0,%1,%2,%3}, [%4];"
                 : "=r"(r0), "=r"(r1), "=r"(r2), "=r"(r3) : "r"(addr));
}
__device__ __forceinline__ void mma_bf16(float* d, const uint32_t* a, const uint32_t* b) {
    asm volatile(
        "mma.sync.aligned.m16n8k16.row.col.f32.bf16.bf16.f32 "
        "{%0,%1,%2,%3}, {%4,%5,%6,%7}, {%8,%9}, {%0,%1,%2,%3};"
        : "+f"(d[0]), "+f"(d[1]), "+f"(d[2]), "+f"(d[3])
        : "r"(a[0]), "r"(a[1]), "r"(a[2]), "r"(a[3]), "r"(b[0]), "r"(b[1]));
}
__device__ __forceinline__ float wsum(float v) {
    #pragma unroll
    for (int m = 16; m; m >>= 1) v += __shfl_xor_sync(0xffffffffu, v, m);
    return v;
}
__device__ __forceinline__ float wmin(float v) {
    #pragma unroll
    for (int m = 16; m; m >>= 1) v = fminf(v, __shfl_xor_sync(0xffffffffu, v, m));
    return v;
}
__device__ __forceinline__ float wmax(float v) {
    #pragma unroll
    for (int m = 16; m; m >>= 1) v = fmaxf(v, __shfl_xor_sync(0xffffffffu, v, m));
    return v;
}

// ---------------- K0: fp32 -> (hi, lo) bf16 split; reset counter ----------------
__global__ void k_convert(const float* __restrict__ X) {
    int idx = blockIdx.x * 256 + threadIdx.x;      // one float4 per thread
    if (idx == 0) g_ctr = 0;
    const float4* X4 = (const float4*)X;
    float4 v = X4[idx];
    float xv[4] = {v.x, v.y, v.z, v.w};
    unsigned short hs[4], ls[4];
    #pragma unroll
    for (int u = 0; u < 4; u++) {
        __nv_bfloat16 h = __float2bfloat16_rn(xv[u]);
        float rem = xv[u] - __bfloat162float(h);
        __nv_bfloat16 l = __float2bfloat16_rn(rem);
        hs[u] = __bfloat16_as_ushort(h);
        ls[u] = __bfloat16_as_ushort(l);
    }
    uint2 hp = make_uint2((uint32_t)hs[0] | ((uint32_t)hs[1] << 16),
                          (uint32_t)hs[2] | ((uint32_t)hs[3] << 16));
    uint2 lp = make_uint2((uint32_t)ls[0] | ((uint32_t)ls[1] << 16),
                          (uint32_t)ls[2] | ((uint32_t)ls[3] << 16));
    ((uint2*)g_xhi)[idx] = hp;
    ((uint2*)g_xlo)[idx] = lp;
}

// ---------------- K1: triangular mma.sync bf16-split GEMM  sim = X X^T ----------------
// 528 CTAs (bi<=bj) x 256 threads, 128 KB smem (R7 proven config).
__global__ void __launch_bounds__(256) k_gemm_mma() {
    extern __shared__ char smem[];
    int tid = threadIdx.x;
    int wid = tid >> 5, lane = tid & 31;

    // triangular block map: blockIdx.x -> (bi, bj), bi <= bj
    int t = blockIdx.x, bi = 0;
    while (t >= 32 - bi) { t -= 32 - bi; bi++; }
    int bj = bi + t;
    int i0 = bi * 128, j0 = bj * 128;

    // ---- load 4 operand tiles into swizzled smem ----
    #pragma unroll
    for (int tt = 0; tt < 4; tt++) {
        const __nv_bfloat16* src = (tt == 0 || tt == 2) ? g_xhi : g_xlo;
        int r0 = (tt < 2) ? i0 : j0;
        char* dst = smem + tt * TILE_B;
        #pragma unroll
        for (int idx = tid; idx < 2048; idx += 256) {
            int r = idx >> 4, c16 = idx & 15;
            uint4 val = *(const uint4*)&src[(size_t)(r0 + r) * DD + c16 * 8];
            *(uint4*)(dst + r * 256 + ((c16 ^ (r & 7)) << 4)) = val;
        }
    }
    __syncthreads();

    int wm = wid >> 2, wn = wid & 3;
    int m_base = wm * 64, n_base = wn * 32;
    int quad = lane >> 3, l7 = lane & 7;
    uint32_t sb = smem_u32(smem);

    float acc[4][4][4];
    #pragma unroll
    for (int mt = 0; mt < 4; mt++)
        #pragma unroll
        for (int nt = 0; nt < 4; nt++)
            #pragma unroll
            for (int q = 0; q < 4; q++) acc[mt][nt][q] = 0.0f;

    // 3 passes: hi*hi, hi*lo, lo*hi
    #pragma unroll
    for (int p = 0; p < 3; p++) {
        uint32_t aoff = (p == 2) ? TILE_B : 0u;
        uint32_t boff = (p == 1) ? 3u * TILE_B : 2u * TILE_B;
        #pragma unroll
        for (int ks = 0; ks < 8; ks++) {
            uint32_t afr[4][4];
            #pragma unroll
            for (int mt = 0; mt < 4; mt++) {
                int ar = m_base + mt * 16 + ((quad & 1) << 3) + l7;
                int ac = (2 * ks + (quad >> 1)) ^ (ar & 7);
                ldsm_x4(afr[mt][0], afr[mt][1], afr[mt][2], afr[mt][3],
                        sb + aoff + ar * 256 + (ac << 4));
            }
            uint32_t bfr[2][4];
            #pragma unroll
            for (int nt2 = 0; nt2 < 2; nt2++) {
                int br = n_base + nt2 * 16 + ((quad >> 1) << 3) + l7;
                int bc = (2 * ks + (quad & 1)) ^ (br & 7);
                ldsm_x4(bfr[nt2][0], bfr[nt2][1], bfr[nt2][2], bfr[nt2][3],
                        sb + boff + br * 256 + (bc << 4));
            }
            #pragma unroll
            for (int mt = 0; mt < 4; mt++)
                #pragma unroll
                for (int nt = 0; nt < 4; nt++)
                    mma_bf16(acc[mt][nt], afr[mt], &bfr[nt >> 1][(nt & 1) * 2]);
        }
    }

    // ---- epilogue 1: normal-orientation writes ----
    int g = lane >> 2, tig = lane & 3;
    #pragma unroll
    for (int mt = 0; mt < 4; mt++) {
        int row0 = i0 + m_base + mt * 16 + g;
        #pragma unroll
        for (int nt = 0; nt < 4; nt++) {
            int col = j0 + n_base + nt * 8 + tig * 2;
            *(float2*)&g_sim[(size_t)row0 * NN + col] = make_float2(acc[mt][nt][0], acc[mt][nt][1]);
            *(float2*)&g_sim[(size_t)(row0 + 8) * NN + col] = make_float2(acc[mt][nt][2], acc[mt][nt][3]);
        }
    }

    // ---- epilogue 2: mirror via smem-staged transpose (off-diagonal only) ----
    if (bi != bj) {
        __syncthreads();                         // all warps done with operand smem
        float* sT = (float*)smem;                // [128 cols][stride 132] = 67.6 KB
        #pragma unroll
        for (int mt = 0; mt < 4; mt++) {
            int rl0 = m_base + mt * 16 + g;
            #pragma unroll
            for (int nt = 0; nt < 4; nt++) {
                int cl = n_base + nt * 8 + tig * 2;
                sT[(cl + 0) * 132 + rl0]     = acc[mt][nt][0];
                sT[(cl + 1) * 132 + rl0]     = acc[mt][nt][1];
                sT[(cl + 0) * 132 + rl0 + 8] = acc[mt][nt][2];
                sT[(cl + 1) * 132 + rl0 + 8] = acc[mt][nt][3];
            }
        }
        __syncthreads();
        #pragma unroll
        for (int it = 0; it < 16; it++) {
            int idx = it * 256 + tid;            // 4096 float4 groups
            int r = idx >> 5, c4 = idx & 31;
            float4 v = *(float4*)&sT[r * 132 + c4 * 4];
            *(float4*)&g_sim[(size_t)(j0 + r) * NN + i0 + c4 * 4] = v;
        }
    }
}

// ---------------- K2: per-row mining, 512 threads/CTA + fused finalize ----------------
#define K2T 512
__global__ void __launch_bounds__(K2T) k_rowpass(const int* __restrict__ tg,
                                                 const float* __restrict__ pm,
                                                 float* __restrict__ out) {
    __shared__ int   stg[NN];
    __shared__ float wr[16][6];
    __shared__ float fin[6];
    __shared__ int   s_is_last;

    int i = blockIdx.x;
    int tid = threadIdx.x;
    int lane = tid & 31, wid = tid >> 5;
    float margin = *pm;
    float m10 = margin / 10.0f;
    float m10f = floorf(m10);

    {
        const int4* tg4 = (const int4*)tg;
        int4* stg4 = (int4*)stg;
        #pragma unroll
        for (int j = tid; j < NN / 4; j += K2T) stg4[j] = tg4[j];
    }
    __syncthreads();
    int ti = stg[i];

    // ---- pass 1: load 8 elements into registers, compute min/max/stats ----
    float sreg[8];
    uint32_t same_mask = 0;
    float minp = 1e9f, maxn = -1e9f;
    float apcnt = 0.f, pps = 0.f, nns = 0.f, ncn = 0.f;
    {
        const float4* row4 = (const float4*)&g_sim[(size_t)i * NN];
        const int4* stg4 = (const int4*)stg;
        #pragma unroll
        for (int v4 = 0; v4 < 2; v4++) {
            int j4 = v4 * K2T + tid;
            float4 s4 = row4[j4];
            int4 t4 = stg4[j4];
            float sv[4] = {s4.x, s4.y, s4.z, s4.w};
            int tv[4] = {t4.x, t4.y, t4.z, t4.w};
            #pragma unroll
            for (int u = 0; u < 4; u++) {
                if (j4 * 4 + u == i) sv[u] = 1.0f;   // exact diagonal (unit-norm rows)
                float s = sv[u];
                sreg[v4 * 4 + u] = s;
                if (tv[u] == ti) {
                    same_mask |= (1u << (v4 * 4 + u));
                    if (s < 1.0f - C_EPS) {
                        minp = fminf(minp, s);
                        apcnt += 1.0f;
                        pps += s;
                    }
                } else {
                    maxn = fmaxf(maxn, s);
                    nns += s;
                    ncn += 1.0f;
                }
            }
        }
    }
    float a = wmin(minp), b = wmax(maxn);
    float c0 = wsum(apcnt), c1 = wsum(pps), c2 = wsum(nns), c3 = wsum(ncn);
    if (lane == 0) {
        wr[wid][0] = a; wr[wid][1] = b; wr[wid][2] = c0;
        wr[wid][3] = c1; wr[wid][4] = c2; wr[wid][5] = c3;
    }
    __syncthreads();
    if (tid == 0) {
        float v0 = 1e9f, v1 = -1e9f, v2 = 0.f, v3 = 0.f, v4 = 0.f, v5 = 0.f;
        #pragma unroll
        for (int w = 0; w < 16; w++) {
            v0 = fminf(v0, wr[w][0]); v1 = fmaxf(v1, wr[w][1]);
            v2 += wr[w][2]; v3 += wr[w][3]; v4 += wr[w][4]; v5 += wr[w][5];
        }
        fin[0] = v0; fin[1] = v1; fin[2] = v2; fin[3] = v3; fin[4] = v4; fin[5] = v5;
    }
    __syncthreads();
    float minP = fin[0], maxN = fin[1];

    // ---- pass 2: mining + softplus sums (pure register math) ----
    float pc = 0.f, nc = 0.f, psum = 0.f, nsum = 0.f;
    #pragma unroll
    for (int e = 0; e < 8; e++) {
        float s = sreg[e];
        if ((same_mask >> e) & 1) {
            if (s < 1.0f - C_EPS && (maxN - s + margin > 0.0f)) {
                pc += 1.0f;
                psum += __logf(1.0f + __expf(-C_BETA * (s - C_BASE)));
            }
        } else {
            if (s + m10 - minP > 0.0f) {
                nc += 1.0f;
                float nv = s + m10 - m10f;
                nsum += __logf(1.0f + __expf(C_ALPHA * (nv - C_BASE)));
            }
        }
    }
    float r0 = wsum(pc), r1 = wsum(nc), r2 = wsum(psum), r3 = wsum(nsum);
    __syncthreads();
    if (lane == 0) {
        wr[wid][0] = r0; wr[wid][1] = r1; wr[wid][2] = r2; wr[wid][3] = r3;
    }
    __syncthreads();
    if (tid == 0) {
        float v0 = 0.f, v1 = 0.f, v2 = 0.f, v3 = 0.f;
        #pragma unroll
        for (int w = 0; w < 16; w++) {
            v0 += wr[w][0]; v1 += wr[w][1]; v2 += wr[w][2]; v3 += wr[w][3];
        }
        g_rowpart[i * 4 + 0] = v0;
        g_rowpart[i * 4 + 1] = v1;
        g_rowpart[i * 4 + 2] = v2;
        g_rowpart[i * 4 + 3] = v3;
        g_rowap[i] = fin[2];
        if (i == NN - 1) {
            g_last[0] = fin[3]; g_last[1] = fin[2];
            g_last[2] = fin[4]; g_last[3] = fin[5];
        }
    }
    __syncthreads();

    // ---- last CTA finalizes ----
    if (tid == 0) {
        __threadfence();
        int done = atomicAdd(&g_ctr, 1);
        s_is_last = (done == NN - 1);
    }
    __syncthreads();
    if (!s_is_last) return;
    __threadfence();

    float lsum = 0.f, cinv = 0.f, lap = 0.f, lan = 0.f, lAP = 0.f;
    for (int k = tid; k < NN; k += K2T) {
        float cp = g_rowpart[k * 4 + 0];
        float cn = g_rowpart[k * 4 + 1];
        float ps = g_rowpart[k * 4 + 2];
        float ns = g_rowpart[k * 4 + 3];
        bool valid = (cp > 0.0f) && (cn > 0.0f);
        if (valid) {
            lsum += (2.0f / C_BETA) * ps / fmaxf(cp, 1.0f)
                  + (2.0f / C_ALPHA) * ns / fmaxf(cn, 1.0f);
            lap += cp;
            lan += cn;
        } else {
            cinv += 1.0f;
        }
        lAP += g_rowap[k];
    }
    lsum = wsum(lsum); cinv = wsum(cinv); lap = wsum(lap); lan = wsum(lan); lAP = wsum(lAP);
    __syncthreads();
    if (lane == 0) {
        wr[wid][0] = lsum; wr[wid][1] = cinv; wr[wid][2] = lap;
        wr[wid][3] = lan;  wr[wid][4] = lAP;
    }
    __syncthreads();
    if (tid == 0) {
        float v0 = 0.f, v1 = 0.f, v2 = 0.f, v3 = 0.f, v4 = 0.f;
        #pragma unroll
        for (int w = 0; w < 16; w++) {
            v0 += wr[w][0]; v1 += wr[w][1]; v2 += wr[w][2];
            v3 += wr[w][3]; v4 += wr[w][4];
        }
        float nf = (float)NN;
        float loss = v0 / nf;
        float prec = v1 / nf;
        float mps = g_last[0] / fmaxf(g_last[1], 1.0f);
        float mns = g_last[2] / fmaxf(g_last[3], 1.0f);
        float la = v2 * 0.5f;
        float ln_ = v3 * 0.5f;
        float rr1 = ln_ / la;
        float s1 = 1.0f / (1.0f + __expf(-rr1));
        float rr2 = ln_ / (v4 * 0.5f);
        float s2 = 1.0f / (1.0f + __expf(-rr2));
        out[0] = loss; out[1] = prec; out[2] = mps; out[3] = mns;
        out[4] = la;   out[5] = ln_;  out[6] = rr1; out[7] = s1;
        out[8] = rr2;  out[9] = s2;
    }
}

// ---------------- host launcher ----------------
extern "C" void kernel_launch(void* const* d_in, const int* in_sizes, int n_in,
                              void* d_out, int out_size) {
    const float* X       = (const float*)d_in[0];
    const int*   targets = (const int*)d_in[1];
    const float* margin  = (const float*)d_in[2];
    float* out = (float*)d_out;

    k_convert<<<(NN * DD / 4) / 256, 256>>>(X);

    cudaFuncSetAttribute(k_gemm_mma, cudaFuncAttributeMaxDynamicSharedMemorySize, 4 * TILE_B);
    k_gemm_mma<<<528, 256, 4 * TILE_B>>>();

    k_rowpass<<<NN, K2T>>>(targets, margin, out);
}

// round 13
// speedup vs baseline: 1.1854x; 1.1854x over previous
#include <cuda_runtime.h>
#include <cuda_bf16.h>
#include <math.h>
#include <stdint.h>

#define NN 4096
#define DD 128
#define C_ALPHA 10.0f
#define C_BETA  2.0f
#define C_BASE  0.7f
#define C_EPS   1e-6f
#define TILE_B 32768

// ---------------- device scratch ----------------
__device__ float g_sim[(size_t)NN * NN];           // 64 MB
__device__ float g_rowpart[NN * 4];
__device__ float g_rowap[NN];
__device__ float g_last[4];
__device__ int   g_ctr;

// ---------------- helpers ----------------
__device__ __forceinline__ uint32_t smem_u32(const void* p) {
    uint32_t a;
    asm("{ .reg .u64 t; cvta.to.shared.u64 t, %1; cvt.u32.u64 %0, t; }" : "=r"(a) : "l"(p));
    return a;
}
__device__ __forceinline__ void ldsm_x4(uint32_t& r0, uint32_t& r1, uint32_t& r2, uint32_t& r3,
                                        uint32_t addr) {
    asm volatile("ldmatrix.sync.aligned.m8n8.x4.shared.b16 {%0,%1,%2,%3}, [%4];"
                 : "=r"(r0), "=r"(r1), "=r"(r2), "=r"(r3) : "r"(addr));
}
__device__ __forceinline__ void mma_bf16(float* d, const uint32_t* a, const uint32_t* b) {
    asm volatile(
        "mma.sync.aligned.m16n8k16.row.col.f32.bf16.bf16.f32 "
        "{%0,%1,%2,%3}, {%4,%5,%6,%7}, {%8,%9}, {%0,%1,%2,%3};"
        : "+f"(d[0]), "+f"(d[1]), "+f"(d[2]), "+f"(d[3])
        : "r"(a[0]), "r"(a[1]), "r"(a[2]), "r"(a[3]), "r"(b[0]), "r"(b[1]));
}
__device__ __forceinline__ float wsum(float v) {
    #pragma unroll
    for (int m = 16; m; m >>= 1) v += __shfl_xor_sync(0xffffffffu, v, m);
    return v;
}
__device__ __forceinline__ float wmin(float v) {
    #pragma unroll
    for (int m = 16; m; m >>= 1) v = fminf(v, __shfl_xor_sync(0xffffffffu, v, m));
    return v;
}
__device__ __forceinline__ float wmax(float v) {
    #pragma unroll
    for (int m = 16; m; m >>= 1) v = fmaxf(v, __shfl_xor_sync(0xffffffffu, v, m));
    return v;
}

// ---- fused convert-load: X fp32 rows r0..r0+127 -> hi/lo bf16 swizzled smem tiles ----
__device__ __forceinline__ void load_tiles_cvt(char* dst_hi, char* dst_lo,
                                               const float* __restrict__ X, int r0, int tid) {
    #pragma unroll
    for (int it = 0; it < 16; it++) {
        int idx = it * 256 + tid;          // 4096 chunks of 4 floats
        int r = idx >> 5, c = idx & 31;    // c: 8B bf16 chunk == 16B fp32 chunk
        float4 v = *(const float4*)&X[(size_t)(r0 + r) * DD + c * 4];
        float xv[4] = {v.x, v.y, v.z, v.w};
        unsigned short hs[4], ls[4];
        #pragma unroll
        for (int u = 0; u < 4; u++) {
            __nv_bfloat16 h = __float2bfloat16_rn(xv[u]);
            float rem = xv[u] - __bfloat162float(h);
            __nv_bfloat16 l = __float2bfloat16_rn(rem);
            hs[u] = __bfloat16_as_ushort(h);
            ls[u] = __bfloat16_as_ushort(l);
        }
        uint2 hp = make_uint2((uint32_t)hs[0] | ((uint32_t)hs[1] << 16),
                              (uint32_t)hs[2] | ((uint32_t)hs[3] << 16));
        uint2 lp = make_uint2((uint32_t)ls[0] | ((uint32_t)ls[1] << 16),
                              (uint32_t)ls[2] | ((uint32_t)ls[3] << 16));
        uint32_t boff = (uint32_t)r * 256 + ((((uint32_t)c >> 1) ^ (r & 7)) << 4) + (c & 1) * 8;
        *(uint2*)(dst_hi + boff) = hp;
        *(uint2*)(dst_lo + boff) = lp;
    }
}

// ---------------- K1: triangular mma.sync bf16-split GEMM  sim = X X^T ----------------
// 528 CTAs (bi<=bj) x 256 threads, 128 KB smem. Inline fp32->bf16 hi/lo conversion.
// Off-diagonal tiles mirrored via smem-staged transpose (padded stride 132 floats).
__global__ void __launch_bounds__(256) k_gemm_mma(const float* __restrict__ X) {
    extern __shared__ char smem[];
    int tid = threadIdx.x;
    int wid = tid >> 5, lane = tid & 31;

    if (blockIdx.x == 0 && tid == 0) g_ctr = 0;   // reset finalize counter each replay

    // triangular block map: blockIdx.x -> (bi, bj), bi <= bj
    int t = blockIdx.x, bi = 0;
    while (t >= 32 - bi) { t -= 32 - bi; bi++; }
    int bj = bi + t;
    int i0 = bi * 128, j0 = bj * 128;

    // buffers: 0=A_hi, 1=A_lo, 2=B_hi, 3=B_lo (R7 layout), converted from fp32 X inline
    load_tiles_cvt(smem,              smem + TILE_B,     X, i0, tid);
    load_tiles_cvt(smem + 2 * TILE_B, smem + 3 * TILE_B, X, j0, tid);
    __syncthreads();

    int wm = wid >> 2, wn = wid & 3;
    int m_base = wm * 64, n_base = wn * 32;
    int quad = lane >> 3, l7 = lane & 7;
    uint32_t sb = smem_u32(smem);

    float acc[4][4][4];
    #pragma unroll
    for (int mt = 0; mt < 4; mt++)
        #pragma unroll
        for (int nt = 0; nt < 4; nt++)
            #pragma unroll
            for (int q = 0; q < 4; q++) acc[mt][nt][q] = 0.0f;

    // 3 passes: hi*hi, hi*lo, lo*hi
    #pragma unroll
    for (int p = 0; p < 3; p++) {
        uint32_t aoff = (p == 2) ? TILE_B : 0u;
        uint32_t boff = (p == 1) ? 3u * TILE_B : 2u * TILE_B;
        #pragma unroll
        for (int ks = 0; ks < 8; ks++) {
            uint32_t afr[4][4];
            #pragma unroll
            for (int mt = 0; mt < 4; mt++) {
                int ar = m_base + mt * 16 + ((quad & 1) << 3) + l7;
                int ac = (2 * ks + (quad >> 1)) ^ (ar & 7);
                ldsm_x4(afr[mt][0], afr[mt][1], afr[mt][2], afr[mt][3],
                        sb + aoff + ar * 256 + (ac << 4));
            }
            uint32_t bfr[2][4];
            #pragma unroll
            for (int nt2 = 0; nt2 < 2; nt2++) {
                int br = n_base + nt2 * 16 + ((quad >> 1) << 3) + l7;
                int bc = (2 * ks + (quad & 1)) ^ (br & 7);
                ldsm_x4(bfr[nt2][0], bfr[nt2][1], bfr[nt2][2], bfr[nt2][3],
                        sb + boff + br * 256 + (bc << 4));
            }
            #pragma unroll
            for (int mt = 0; mt < 4; mt++)
                #pragma unroll
                for (int nt = 0; nt < 4; nt++)
                    mma_bf16(acc[mt][nt], afr[mt], &bfr[nt >> 1][(nt & 1) * 2]);
        }
    }

    // ---- epilogue 1: normal-orientation writes ----
    int g = lane >> 2, tig = lane & 3;
    #pragma unroll
    for (int mt = 0; mt < 4; mt++) {
        int row0 = i0 + m_base + mt * 16 + g;
        #pragma unroll
        for (int nt = 0; nt < 4; nt++) {
            int col = j0 + n_base + nt * 8 + tig * 2;
            *(float2*)&g_sim[(size_t)row0 * NN + col] = make_float2(acc[mt][nt][0], acc[mt][nt][1]);
            *(float2*)&g_sim[(size_t)(row0 + 8) * NN + col] = make_float2(acc[mt][nt][2], acc[mt][nt][3]);
        }
    }

    // ---- epilogue 2: mirror via smem-staged transpose (off-diagonal only) ----
    if (bi != bj) {
        __syncthreads();                         // all warps done with operand smem
        float* sT = (float*)smem;                // [128 cols][stride 132] = 67.6 KB
        #pragma unroll
        for (int mt = 0; mt < 4; mt++) {
            int rl0 = m_base + mt * 16 + g;
            #pragma unroll
            for (int nt = 0; nt < 4; nt++) {
                int cl = n_base + nt * 8 + tig * 2;
                sT[(cl + 0) * 132 + rl0]     = acc[mt][nt][0];
                sT[(cl + 1) * 132 + rl0]     = acc[mt][nt][1];
                sT[(cl + 0) * 132 + rl0 + 8] = acc[mt][nt][2];
                sT[(cl + 1) * 132 + rl0 + 8] = acc[mt][nt][3];
            }
        }
        __syncthreads();
        #pragma unroll
        for (int it = 0; it < 16; it++) {
            int idx = it * 256 + tid;            // 4096 float4 groups
            int r = idx >> 5, c4 = idx & 31;
            float4 v = *(float4*)&sT[r * 132 + c4 * 4];
            *(float4*)&g_sim[(size_t)(j0 + r) * NN + i0 + c4 * 4] = v;
        }
    }
}

// ---------------- K2: per-row mining (register-resident row) + fused finalize ----------------
__global__ void __launch_bounds__(256) k_rowpass(const int* __restrict__ tg,
                                                 const float* __restrict__ pm,
                                                 float* __restrict__ out) {
    __shared__ int   stg[NN];
    __shared__ float wr[8][6];
    __shared__ float fin[6];
    __shared__ int   s_is_last;

    int i = blockIdx.x;
    int tid = threadIdx.x;
    int lane = tid & 31, wid = tid >> 5;
    float margin = *pm;
    float m10 = margin / 10.0f;
    float m10f = floorf(m10);

    {
        const int4* tg4 = (const int4*)tg;
        int4* stg4 = (int4*)stg;
        for (int j = tid; j < NN / 4; j += 256) stg4[j] = tg4[j];
    }
    __syncthreads();
    int ti = stg[i];

    // ---- pass 1: load 16 elements into registers, compute min/max/stats ----
    float sreg[16];
    uint32_t same_mask = 0;
    float minp = 1e9f, maxn = -1e9f;
    float apcnt = 0.f, pps = 0.f, nns = 0.f, ncn = 0.f;
    {
        const float4* row4 = (const float4*)&g_sim[(size_t)i * NN];
        const int4* stg4 = (const int4*)stg;
        #pragma unroll
        for (int v4 = 0; v4 < 4; v4++) {
            int j4 = v4 * 256 + tid;
            float4 s4 = row4[j4];
            int4 t4 = stg4[j4];
            float sv[4] = {s4.x, s4.y, s4.z, s4.w};
            int tv[4] = {t4.x, t4.y, t4.z, t4.w};
            #pragma unroll
            for (int u = 0; u < 4; u++) {
                if (j4 * 4 + u == i) sv[u] = 1.0f;   // exact diagonal (unit-norm rows)
                float s = sv[u];
                sreg[v4 * 4 + u] = s;
                if (tv[u] == ti) {
                    same_mask |= (1u << (v4 * 4 + u));
                    if (s < 1.0f - C_EPS) {
                        minp = fminf(minp, s);
                        apcnt += 1.0f;
                        pps += s;
                    }
                } else {
                    maxn = fmaxf(maxn, s);
                    nns += s;
                    ncn += 1.0f;
                }
            }
        }
    }
    float a = wmin(minp), b = wmax(maxn);
    float c0 = wsum(apcnt), c1 = wsum(pps), c2 = wsum(nns), c3 = wsum(ncn);
    if (lane == 0) {
        wr[wid][0] = a; wr[wid][1] = b; wr[wid][2] = c0;
        wr[wid][3] = c1; wr[wid][4] = c2; wr[wid][5] = c3;
    }
    __syncthreads();
    if (tid == 0) {
        float v0 = 1e9f, v1 = -1e9f, v2 = 0.f, v3 = 0.f, v4 = 0.f, v5 = 0.f;
        #pragma unroll
        for (int w = 0; w < 8; w++) {
            v0 = fminf(v0, wr[w][0]); v1 = fmaxf(v1, wr[w][1]);
            v2 += wr[w][2]; v3 += wr[w][3]; v4 += wr[w][4]; v5 += wr[w][5];
        }
        fin[0] = v0; fin[1] = v1; fin[2] = v2; fin[3] = v3; fin[4] = v4; fin[5] = v5;
    }
    __syncthreads();
    float minP = fin[0], maxN = fin[1];

    // ---- pass 2: mining + softplus sums (pure register math) ----
    float pc = 0.f, nc = 0.f, psum = 0.f, nsum = 0.f;
    #pragma unroll
    for (int e = 0; e < 16; e++) {
        float s = sreg[e];
        if ((same_mask >> e) & 1) {
            if (s < 1.0f - C_EPS && (maxN - s + margin > 0.0f)) {
                pc += 1.0f;
                psum += __logf(1.0f + __expf(-C_BETA * (s - C_BASE)));
            }
        } else {
            if (s + m10 - minP > 0.0f) {
                nc += 1.0f;
                float nv = s + m10 - m10f;
                nsum += __logf(1.0f + __expf(C_ALPHA * (nv - C_BASE)));
            }
        }
    }
    float r0 = wsum(pc), r1 = wsum(nc), r2 = wsum(psum), r3 = wsum(nsum);
    __syncthreads();
    if (lane == 0) {
        wr[wid][0] = r0; wr[wid][1] = r1; wr[wid][2] = r2; wr[wid][3] = r3;
    }
    __syncthreads();
    if (tid == 0) {
        float v0 = 0.f, v1 = 0.f, v2 = 0.f, v3 = 0.f;
        #pragma unroll
        for (int w = 0; w < 8; w++) {
            v0 += wr[w][0]; v1 += wr[w][1]; v2 += wr[w][2]; v3 += wr[w][3];
        }
        g_rowpart[i * 4 + 0] = v0;
        g_rowpart[i * 4 + 1] = v1;
        g_rowpart[i * 4 + 2] = v2;
        g_rowpart[i * 4 + 3] = v3;
        g_rowap[i] = fin[2];
        if (i == NN - 1) {
            g_last[0] = fin[3]; g_last[1] = fin[2];
            g_last[2] = fin[4]; g_last[3] = fin[5];
        }
    }
    __syncthreads();

    // ---- last CTA finalizes ----
    if (tid == 0) {
        __threadfence();
        int done = atomicAdd(&g_ctr, 1);
        s_is_last = (done == NN - 1);
    }
    __syncthreads();
    if (!s_is_last) return;
    __threadfence();

    float lsum = 0.f, cinv = 0.f, lap = 0.f, lan = 0.f, lAP = 0.f;
    for (int k = tid; k < NN; k += 256) {
        float cp = g_rowpart[k * 4 + 0];
        float cn = g_rowpart[k * 4 + 1];
        float ps = g_rowpart[k * 4 + 2];
        float ns = g_rowpart[k * 4 + 3];
        bool valid = (cp > 0.0f) && (cn > 0.0f);
        if (valid) {
            lsum += (2.0f / C_BETA) * ps / fmaxf(cp, 1.0f)
                  + (2.0f / C_ALPHA) * ns / fmaxf(cn, 1.0f);
            lap += cp;
            lan += cn;
        } else {
            cinv += 1.0f;
        }
        lAP += g_rowap[k];
    }
    lsum = wsum(lsum); cinv = wsum(cinv); lap = wsum(lap); lan = wsum(lan); lAP = wsum(lAP);
    __syncthreads();
    if (lane == 0) {
        wr[wid][0] = lsum; wr[wid][1] = cinv; wr[wid][2] = lap;
        wr[wid][3] = lan;  wr[wid][4] = lAP;
    }
    __syncthreads();
    if (tid == 0) {
        float v0 = 0.f, v1 = 0.f, v2 = 0.f, v3 = 0.f, v4 = 0.f;
        #pragma unroll
        for (int w = 0; w < 8; w++) {
            v0 += wr[w][0]; v1 += wr[w][1]; v2 += wr[w][2];
            v3 += wr[w][3]; v4 += wr[w][4];
        }
        float nf = (float)NN;
        float loss = v0 / nf;
        float prec = v1 / nf;
        float mps = g_last[0] / fmaxf(g_last[1], 1.0f);
        float mns = g_last[2] / fmaxf(g_last[3], 1.0f);
        float la = v2 * 0.5f;
        float ln_ = v3 * 0.5f;
        float rr1 = ln_ / la;
        float s1 = 1.0f / (1.0f + __expf(-rr1));
        float rr2 = ln_ / (v4 * 0.5f);
        float s2 = 1.0f / (1.0f + __expf(-rr2));
        out[0] = loss; out[1] = prec; out[2] = mps; out[3] = mns;
        out[4] = la;   out[5] = ln_;  out[6] = rr1; out[7] = s1;
        out[8] = rr2;  out[9] = s2;
    }
}

// ---------------- host launcher ----------------
extern "C" void kernel_launch(void* const* d_in, const int* in_sizes, int n_in,
                              void* d_out, int out_size) {
    const float* X       = (const float*)d_in[0];
    const int*   targets = (const int*)d_in[1];
    const float* margin  = (const float*)d_in[2];
    float* out = (float*)d_out;

    cudaFuncSetAttribute(k_gemm_mma, cudaFuncAttributeMaxDynamicSharedMemorySize, 4 * TILE_B);
    k_gemm_mma<<<528, 256, 4 * TILE_B>>>(X);

    k_rowpass<<<NN, 256>>>(targets, margin, out);
}

// round 14
// speedup vs baseline: 1.3010x; 1.0975x over previous
#include <cuda_runtime.h>
#include <cuda_bf16.h>
#include <math.h>
#include <stdint.h>

#define NN 4096
#define DD 128
#define C_ALPHA 10.0f
#define C_BETA  2.0f
#define C_BASE  0.7f
#define C_EPS   1e-6f
#define TILE_B 32768

// ---------------- device scratch ----------------
__device__ __nv_bfloat16 g_xhi[(size_t)NN * DD];   // 1 MB
__device__ __nv_bfloat16 g_xlo[(size_t)NN * DD];   // 1 MB
__device__ float g_sim[(size_t)NN * NN];           // 64 MB
__device__ float g_rowpart[NN * 4];
__device__ float g_last[4];
__device__ int   g_ctr;

// ---------------- helpers ----------------
__device__ __forceinline__ uint32_t smem_u32(const void* p) {
    uint32_t a;
    asm("{ .reg .u64 t; cvta.to.shared.u64 t, %1; cvt.u32.u64 %0, t; }" : "=r"(a) : "l"(p));
    return a;
}
__device__ __forceinline__ void ldsm_x4(uint32_t& r0, uint32_t& r1, uint32_t& r2, uint32_t& r3,
                                        uint32_t addr) {
    asm volatile("ldmatrix.sync.aligned.m8n8.x4.shared.b16 {%0,%1,%2,%3}, [%4];"
                 : "=r"(r0), "=r"(r1), "=r"(r2), "=r"(r3) : "r"(addr));
}
__device__ __forceinline__ void mma_bf16(float* d, const uint32_t* a, const uint32_t* b) {
    asm volatile(
        "mma.sync.aligned.m16n8k16.row.col.f32.bf16.bf16.f32 "
        "{%0,%1,%2,%3}, {%4,%5,%6,%7}, {%8,%9}, {%0,%1,%2,%3};"
        : "+f"(d[0]), "+f"(d[1]), "+f"(d[2]), "+f"(d[3])
        : "r"(a[0]), "r"(a[1]), "r"(a[2]), "r"(a[3]), "r"(b[0]), "r"(b[1]));
}
__device__ __forceinline__ float wsum(float v) {
    #pragma unroll
    for (int m = 16; m; m >>= 1) v += __shfl_xor_sync(0xffffffffu, v, m);
    return v;
}
__device__ __forceinline__ float wmin(float v) {
    #pragma unroll
    for (int m = 16; m; m >>= 1) v = fminf(v, __shfl_xor_sync(0xffffffffu, v, m));
    return v;
}
__device__ __forceinline__ float wmax(float v) {
    #pragma unroll
    for (int m = 16; m; m >>= 1) v = fmaxf(v, __shfl_xor_sync(0xffffffffu, v, m));
    return v;
}

// ---------------- K0: fp32 -> (hi, lo) bf16 split; reset counter ----------------
__global__ void k_convert(const float* __restrict__ X) {
    int idx = blockIdx.x * 256 + threadIdx.x;      // one float4 per thread
    if (idx == 0) g_ctr = 0;
    const float4* X4 = (const float4*)X;
    float4 v = X4[idx];
    float xv[4] = {v.x, v.y, v.z, v.w};
    unsigned short hs[4], ls[4];
    #pragma unroll
    for (int u = 0; u < 4; u++) {
        __nv_bfloat16 h = __float2bfloat16_rn(xv[u]);
        float rem = xv[u] - __bfloat162float(h);
        __nv_bfloat16 l = __float2bfloat16_rn(rem);
        hs[u] = __bfloat16_as_ushort(h);
        ls[u] = __bfloat16_as_ushort(l);
    }
    uint2 hp = make_uint2((uint32_t)hs[0] | ((uint32_t)hs[1] << 16),
                          (uint32_t)hs[2] | ((uint32_t)hs[3] << 16));
    uint2 lp = make_uint2((uint32_t)ls[0] | ((uint32_t)ls[1] << 16),
                          (uint32_t)ls[2] | ((uint32_t)ls[3] << 16));
    ((uint2*)g_xhi)[idx] = hp;
    ((uint2*)g_xlo)[idx] = lp;
}

// ---------------- K1: triangular mma.sync bf16-split GEMM  sim = X X^T ----------------
// 528 CTAs (bi<=bj) x 256 threads, 128 KB smem (R7 proven config).
__global__ void __launch_bounds__(256) k_gemm_mma() {
    extern __shared__ char smem[];
    int tid = threadIdx.x;
    int wid = tid >> 5, lane = tid & 31;

    // triangular block map: blockIdx.x -> (bi, bj), bi <= bj
    int t = blockIdx.x, bi = 0;
    while (t >= 32 - bi) { t -= 32 - bi; bi++; }
    int bj = bi + t;
    int i0 = bi * 128, j0 = bj * 128;

    // ---- load 4 operand tiles into swizzled smem ----
    #pragma unroll
    for (int tt = 0; tt < 4; tt++) {
        const __nv_bfloat16* src = (tt == 0 || tt == 2) ? g_xhi : g_xlo;
        int r0 = (tt < 2) ? i0 : j0;
        char* dst = smem + tt * TILE_B;
        #pragma unroll
        for (int idx = tid; idx < 2048; idx += 256) {
            int r = idx >> 4, c16 = idx & 15;
            uint4 val = *(const uint4*)&src[(size_t)(r0 + r) * DD + c16 * 8];
            *(uint4*)(dst + r * 256 + ((c16 ^ (r & 7)) << 4)) = val;
        }
    }
    __syncthreads();

    int wm = wid >> 2, wn = wid & 3;
    int m_base = wm * 64, n_base = wn * 32;
    int quad = lane >> 3, l7 = lane & 7;
    uint32_t sb = smem_u32(smem);

    float acc[4][4][4];
    #pragma unroll
    for (int mt = 0; mt < 4; mt++)
        #pragma unroll
        for (int nt = 0; nt < 4; nt++)
            #pragma unroll
            for (int q = 0; q < 4; q++) acc[mt][nt][q] = 0.0f;

    // 3 passes: hi*hi, hi*lo, lo*hi
    #pragma unroll
    for (int p = 0; p < 3; p++) {
        uint32_t aoff = (p == 2) ? TILE_B : 0u;
        uint32_t boff = (p == 1) ? 3u * TILE_B : 2u * TILE_B;
        #pragma unroll
        for (int ks = 0; ks < 8; ks++) {
            uint32_t afr[4][4];
            #pragma unroll
            for (int mt = 0; mt < 4; mt++) {
                int ar = m_base + mt * 16 + ((quad & 1) << 3) + l7;
                int ac = (2 * ks + (quad >> 1)) ^ (ar & 7);
                ldsm_x4(afr[mt][0], afr[mt][1], afr[mt][2], afr[mt][3],
                        sb + aoff + ar * 256 + (ac << 4));
            }
            uint32_t bfr[2][4];
            #pragma unroll
            for (int nt2 = 0; nt2 < 2; nt2++) {
                int br = n_base + nt2 * 16 + ((quad >> 1) << 3) + l7;
                int bc = (2 * ks + (quad & 1)) ^ (br & 7);
                ldsm_x4(bfr[nt2][0], bfr[nt2][1], bfr[nt2][2], bfr[nt2][3],
                        sb + boff + br * 256 + (bc << 4));
            }
            #pragma unroll
            for (int mt = 0; mt < 4; mt++)
                #pragma unroll
                for (int nt = 0; nt < 4; nt++)
                    mma_bf16(acc[mt][nt], afr[mt], &bfr[nt >> 1][(nt & 1) * 2]);
        }
    }

    // ---- epilogue 1: normal-orientation writes ----
    int g = lane >> 2, tig = lane & 3;
    #pragma unroll
    for (int mt = 0; mt < 4; mt++) {
        int row0 = i0 + m_base + mt * 16 + g;
        #pragma unroll
        for (int nt = 0; nt < 4; nt++) {
            int col = j0 + n_base + nt * 8 + tig * 2;
            *(float2*)&g_sim[(size_t)row0 * NN + col] = make_float2(acc[mt][nt][0], acc[mt][nt][1]);
            *(float2*)&g_sim[(size_t)(row0 + 8) * NN + col] = make_float2(acc[mt][nt][2], acc[mt][nt][3]);
        }
    }

    // ---- epilogue 2: mirror via smem-staged transpose (off-diagonal only) ----
    if (bi != bj) {
        __syncthreads();                         // all warps done with operand smem
        float* sT = (float*)smem;                // [128 cols][stride 132] = 67.6 KB
        #pragma unroll
        for (int mt = 0; mt < 4; mt++) {
            int rl0 = m_base + mt * 16 + g;
            #pragma unroll
            for (int nt = 0; nt < 4; nt++) {
                int cl = n_base + nt * 8 + tig * 2;
                sT[(cl + 0) * 132 + rl0]     = acc[mt][nt][0];
                sT[(cl + 1) * 132 + rl0]     = acc[mt][nt][1];
                sT[(cl + 0) * 132 + rl0 + 8] = acc[mt][nt][2];
                sT[(cl + 1) * 132 + rl0 + 8] = acc[mt][nt][3];
            }
        }
        __syncthreads();
        #pragma unroll
        for (int it = 0; it < 16; it++) {
            int idx = it * 256 + tid;            // 4096 float4 groups
            int r = idx >> 5, c4 = idx & 31;
            float4 v = *(float4*)&sT[r * 132 + c4 * 4];
            *(float4*)&g_sim[(size_t)(j0 + r) * NN + i0 + c4 * 4] = v;
        }
    }
}

// ---------------- K2: slim per-row mining + fused finalize ----------------
// pass1: only min_pos / max_neg / membership mask (counts via popc + algebra).
// pps/nns computed only in the last-row CTA. length_AP via class histogram in finalize.
__global__ void __launch_bounds__(256) k_rowpass(const int* __restrict__ tg,
                                                 const float* __restrict__ pm,
                                                 float* __restrict__ out) {
    __shared__ int   stg[NN];
    __shared__ float wr[8][5];
    __shared__ float fin[5];
    __shared__ int   s_is_last;
    __shared__ int   shist[64];

    int i = blockIdx.x;
    int tid = threadIdx.x;
    int lane = tid & 31, wid = tid >> 5;
    float margin = *pm;
    float m10 = margin / 10.0f;
    float m10f = floorf(m10);

    {
        const int4* tg4 = (const int4*)tg;
        int4* stg4 = (int4*)stg;
        for (int j = tid; j < NN / 4; j += 256) stg4[j] = tg4[j];
    }
    __syncthreads();
    int ti = stg[i];
    bool lastrow = (i == NN - 1);

    // ---- pass 1: load 16 elements into registers; min_pos / max_neg / same mask ----
    float sreg[16];
    uint32_t same_mask = 0;
    float minp = 1e9f, maxn = -1e9f;
    {
        const float4* row4 = (const float4*)&g_sim[(size_t)i * NN];
        const int4* stg4 = (const int4*)stg;
        #pragma unroll
        for (int v4 = 0; v4 < 4; v4++) {
            int j4 = v4 * 256 + tid;
            float4 s4 = row4[j4];
            int4 t4 = stg4[j4];
            float sv[4] = {s4.x, s4.y, s4.z, s4.w};
            int tv[4] = {t4.x, t4.y, t4.z, t4.w};
            #pragma unroll
            for (int u = 0; u < 4; u++) {
                int j = j4 * 4 + u;
                bool diag = (j == i);
                float s = diag ? 1.0f : sv[u];    // exact diagonal (unit-norm rows)
                sreg[v4 * 4 + u] = s;
                if (tv[u] == ti) {
                    same_mask |= (1u << (v4 * 4 + u));
                    if (!diag) minp = fminf(minp, s);
                } else {
                    maxn = fmaxf(maxn, s);
                }
            }
        }
    }
    float scnt = (float)__popc(same_mask);        // same-class count incl. diagonal

    // last-row CTA only: pre-mining sums (exact baseline order)
    float pps = 0.f, nns = 0.f;
    if (lastrow) {
        #pragma unroll
        for (int e = 0; e < 16; e++) {
            float s = sreg[e];
            if ((same_mask >> e) & 1) {
                if (s < 1.0f - C_EPS) pps += s;
            } else {
                nns += s;
            }
        }
    }

    float a = wmin(minp), b = wmax(maxn);
    float c0 = wsum(scnt), c1 = wsum(pps), c2 = wsum(nns);
    if (lane == 0) {
        wr[wid][0] = a; wr[wid][1] = b; wr[wid][2] = c0;
        wr[wid][3] = c1; wr[wid][4] = c2;
    }
    __syncthreads();
    if (tid == 0) {
        float v0 = 1e9f, v1 = -1e9f, v2 = 0.f, v3 = 0.f, v4 = 0.f;
        #pragma unroll
        for (int w = 0; w < 8; w++) {
            v0 = fminf(v0, wr[w][0]); v1 = fmaxf(v1, wr[w][1]);
            v2 += wr[w][2]; v3 += wr[w][3]; v4 += wr[w][4];
        }
        fin[0] = v0; fin[1] = v1; fin[2] = v2; fin[3] = v3; fin[4] = v4;
    }
    __syncthreads();
    float minP = fin[0], maxN = fin[1];

    // ---- pass 2: mining + softplus sums (pure register math, baseline forms) ----
    float pc = 0.f, nc = 0.f, psum = 0.f, nsum = 0.f;
    #pragma unroll
    for (int e = 0; e < 16; e++) {
        float s = sreg[e];
        if ((same_mask >> e) & 1) {
            if (s < 1.0f - C_EPS && (maxN - s + margin > 0.0f)) {
                pc += 1.0f;
                psum += __logf(1.0f + __expf(-C_BETA * (s - C_BASE)));
            }
        } else {
            if (s + m10 - minP > 0.0f) {
                nc += 1.0f;
                float nv = s + m10 - m10f;
                nsum += __logf(1.0f + __expf(C_ALPHA * (nv - C_BASE)));
            }
        }
    }
    float r0 = wsum(pc), r1 = wsum(nc), r2 = wsum(psum), r3 = wsum(nsum);
    __syncthreads();
    if (lane == 0) {
        wr[wid][0] = r0; wr[wid][1] = r1; wr[wid][2] = r2; wr[wid][3] = r3;
    }
    __syncthreads();
    if (tid == 0) {
        float v0 = 0.f, v1 = 0.f, v2 = 0.f, v3 = 0.f;
        #pragma unroll
        for (int w = 0; w < 8; w++) {
            v0 += wr[w][0]; v1 += wr[w][1]; v2 += wr[w][2]; v3 += wr[w][3];
        }
        g_rowpart[i * 4 + 0] = v0;
        g_rowpart[i * 4 + 1] = v1;
        g_rowpart[i * 4 + 2] = v2;
        g_rowpart[i * 4 + 3] = v3;
        if (lastrow) {
            g_last[0] = fin[3];                 // pre-mining pos sim sum
            g_last[1] = fin[2] - 1.0f;          // pos_mask count = |class| - 1
            g_last[2] = fin[4];                 // pre-mining neg sim sum
            g_last[3] = (float)NN - fin[2];     // neg count
        }
    }
    __syncthreads();

    // ---- last CTA finalizes ----
    if (tid == 0) {
        __threadfence();
        int done = atomicAdd(&g_ctr, 1);
        s_is_last = (done == NN - 1);
    }
    __syncthreads();
    if (!s_is_last) return;
    __threadfence();

    // class histogram from smem-resident targets -> length_AP = sum(cnt^2) - NN
    if (tid < 64) shist[tid] = 0;
    __syncthreads();
    for (int j = tid; j < NN; j += 256) atomicAdd(&shist[stg[j]], 1);
    __syncthreads();

    float lsum = 0.f, cinv = 0.f, lap = 0.f, lan = 0.f;
    for (int k = tid; k < NN; k += 256) {
        float cp = g_rowpart[k * 4 + 0];
        float cn = g_rowpart[k * 4 + 1];
        float ps = g_rowpart[k * 4 + 2];
        float ns = g_rowpart[k * 4 + 3];
        bool valid = (cp > 0.0f) && (cn > 0.0f);
        if (valid) {
            lsum += (2.0f / C_BETA) * ps / fmaxf(cp, 1.0f)
                  + (2.0f / C_ALPHA) * ns / fmaxf(cn, 1.0f);
            lap += cp;
            lan += cn;
        } else {
            cinv += 1.0f;
        }
    }
    lsum = wsum(lsum); cinv = wsum(cinv); lap = wsum(lap); lan = wsum(lan);
    __syncthreads();
    if (lane == 0) {
        wr[wid][0] = lsum; wr[wid][1] = cinv; wr[wid][2] = lap; wr[wid][3] = lan;
    }
    __syncthreads();
    if (tid == 0) {
        float v0 = 0.f, v1 = 0.f, v2 = 0.f, v3 = 0.f;
        #pragma unroll
        for (int w = 0; w < 8; w++) {
            v0 += wr[w][0]; v1 += wr[w][1]; v2 += wr[w][2]; v3 += wr[w][3];
        }
        long long sum2 = 0;
        #pragma unroll
        for (int c = 0; c < 64; c++) {
            long long h = shist[c];
            sum2 += h * h;
        }
        float lAP = (float)(sum2 - NN);

        float nf = (float)NN;
        float loss = v0 / nf;
        float prec = v1 / nf;
        float mps = g_last[0] / fmaxf(g_last[1], 1.0f);
        float mns = g_last[2] / fmaxf(g_last[3], 1.0f);
        float la = v2 * 0.5f;
        float ln_ = v3 * 0.5f;
        float rr1 = ln_ / la;
        float s1 = 1.0f / (1.0f + __expf(-rr1));
        float rr2 = ln_ / (lAP * 0.5f);
        float s2 = 1.0f / (1.0f + __expf(-rr2));
        out[0] = loss; out[1] = prec; out[2] = mps; out[3] = mns;
        out[4] = la;   out[5] = ln_;  out[6] = rr1; out[7] = s1;
        out[8] = rr2;  out[9] = s2;
    }
}

// ---------------- host launcher ----------------
extern "C" void kernel_launch(void* const* d_in, const int* in_sizes, int n_in,
                              void* d_out, int out_size) {
    const float* X       = (const float*)d_in[0];
    const int*   targets = (const int*)d_in[1];
    const float* margin  = (const float*)d_in[2];
    float* out = (float*)d_out;

    k_convert<<<(NN * DD / 4) / 256, 256>>>(X);

    cudaFuncSetAttribute(k_gemm_mma, cudaFuncAttributeMaxDynamicSharedMemorySize, 4 * TILE_B);
    k_gemm_mma<<<528, 256, 4 * TILE_B>>>();

    k_rowpass<<<NN, 256>>>(targets, margin, out);
}

// round 15
// speedup vs baseline: 1.3322x; 1.0240x over previous
#include <cuda_runtime.h>
#include <cuda_bf16.h>
#include <math.h>
#include <stdint.h>

#define NN 4096
#define DD 128
#define C_ALPHA 10.0f
#define C_BETA  2.0f
#define C_BASE  0.7f
#define C_EPS   1e-6f
#define TILE_B 32768

// ---------------- device scratch ----------------
__device__ __nv_bfloat16 g_xhi[(size_t)NN * DD];   // 1 MB
__device__ __nv_bfloat16 g_xlo[(size_t)NN * DD];   // 1 MB
__device__ float g_sim[(size_t)NN * NN];           // 64 MB
__device__ float g_rowpart[NN * 4];
__device__ float g_last[4];
__device__ int   g_ctr;

// ---------------- helpers ----------------
__device__ __forceinline__ uint32_t smem_u32(const void* p) {
    uint32_t a;
    asm("{ .reg .u64 t; cvta.to.shared.u64 t, %1; cvt.u32.u64 %0, t; }" : "=r"(a) : "l"(p));
    return a;
}
__device__ __forceinline__ void ldsm_x4(uint32_t& r0, uint32_t& r1, uint32_t& r2, uint32_t& r3,
                                        uint32_t addr) {
    asm volatile("ldmatrix.sync.aligned.m8n8.x4.shared.b16 {%0,%1,%2,%3}, [%4];"
                 : "=r"(r0), "=r"(r1), "=r"(r2), "=r"(r3) : "r"(addr));
}
__device__ __forceinline__ void mma_bf16(float* d, const uint32_t* a, const uint32_t* b) {
    asm volatile(
        "mma.sync.aligned.m16n8k16.row.col.f32.bf16.bf16.f32 "
        "{%0,%1,%2,%3}, {%4,%5,%6,%7}, {%8,%9}, {%0,%1,%2,%3};"
        : "+f"(d[0]), "+f"(d[1]), "+f"(d[2]), "+f"(d[3])
        : "r"(a[0]), "r"(a[1]), "r"(a[2]), "r"(a[3]), "r"(b[0]), "r"(b[1]));
}
__device__ __forceinline__ float wsum(float v) {
    #pragma unroll
    for (int m = 16; m; m >>= 1) v += __shfl_xor_sync(0xffffffffu, v, m);
    return v;
}
__device__ __forceinline__ float wmin(float v) {
    #pragma unroll
    for (int m = 16; m; m >>= 1) v = fminf(v, __shfl_xor_sync(0xffffffffu, v, m));
    return v;
}
__device__ __forceinline__ float wmax(float v) {
    #pragma unroll
    for (int m = 16; m; m >>= 1) v = fmaxf(v, __shfl_xor_sync(0xffffffffu, v, m));
    return v;
}

// ---------------- K0: fp32 -> (hi, lo) bf16 split; reset counter ----------------
__global__ void k_convert(const float* __restrict__ X) {
    int idx = blockIdx.x * 256 + threadIdx.x;      // one float4 per thread
    if (idx == 0) g_ctr = 0;
    const float4* X4 = (const float4*)X;
    float4 v = X4[idx];
    float xv[4] = {v.x, v.y, v.z, v.w};
    unsigned short hs[4], ls[4];
    #pragma unroll
    for (int u = 0; u < 4; u++) {
        __nv_bfloat16 h = __float2bfloat16_rn(xv[u]);
        float rem = xv[u] - __bfloat162float(h);
        __nv_bfloat16 l = __float2bfloat16_rn(rem);
        hs[u] = __bfloat16_as_ushort(h);
        ls[u] = __bfloat16_as_ushort(l);
    }
    uint2 hp = make_uint2((uint32_t)hs[0] | ((uint32_t)hs[1] << 16),
                          (uint32_t)hs[2] | ((uint32_t)hs[3] << 16));
    uint2 lp = make_uint2((uint32_t)ls[0] | ((uint32_t)ls[1] << 16),
                          (uint32_t)ls[2] | ((uint32_t)ls[3] << 16));
    ((uint2*)g_xhi)[idx] = hp;
    ((uint2*)g_xlo)[idx] = lp;
}

// ---------------- K1: triangular mma.sync bf16-split GEMM  sim = X X^T ----------------
// 528 CTAs (bi<=bj) x 256 threads, 128 KB smem (R7 proven config).
__global__ void __launch_bounds__(256) k_gemm_mma() {
    extern __shared__ char smem[];
    int tid = threadIdx.x;
    int wid = tid >> 5, lane = tid & 31;

    // triangular block map: blockIdx.x -> (bi, bj), bi <= bj
    int t = blockIdx.x, bi = 0;
    while (t >= 32 - bi) { t -= 32 - bi; bi++; }
    int bj = bi + t;
    int i0 = bi * 128, j0 = bj * 128;

    // ---- load 4 operand tiles into swizzled smem ----
    #pragma unroll
    for (int tt = 0; tt < 4; tt++) {
        const __nv_bfloat16* src = (tt == 0 || tt == 2) ? g_xhi : g_xlo;
        int r0 = (tt < 2) ? i0 : j0;
        char* dst = smem + tt * TILE_B;
        #pragma unroll
        for (int idx = tid; idx < 2048; idx += 256) {
            int r = idx >> 4, c16 = idx & 15;
            uint4 val = *(const uint4*)&src[(size_t)(r0 + r) * DD + c16 * 8];
            *(uint4*)(dst + r * 256 + ((c16 ^ (r & 7)) << 4)) = val;
        }
    }
    __syncthreads();

    int wm = wid >> 2, wn = wid & 3;
    int m_base = wm * 64, n_base = wn * 32;
    int quad = lane >> 3, l7 = lane & 7;
    uint32_t sb = smem_u32(smem);

    float acc[4][4][4];
    #pragma unroll
    for (int mt = 0; mt < 4; mt++)
        #pragma unroll
        for (int nt = 0; nt < 4; nt++)
            #pragma unroll
            for (int q = 0; q < 4; q++) acc[mt][nt][q] = 0.0f;

    // 3 passes: hi*hi, hi*lo, lo*hi
    #pragma unroll
    for (int p = 0; p < 3; p++) {
        uint32_t aoff = (p == 2) ? TILE_B : 0u;
        uint32_t boff = (p == 1) ? 3u * TILE_B : 2u * TILE_B;
        #pragma unroll
        for (int ks = 0; ks < 8; ks++) {
            uint32_t afr[4][4];
            #pragma unroll
            for (int mt = 0; mt < 4; mt++) {
                int ar = m_base + mt * 16 + ((quad & 1) << 3) + l7;
                int ac = (2 * ks + (quad >> 1)) ^ (ar & 7);
                ldsm_x4(afr[mt][0], afr[mt][1], afr[mt][2], afr[mt][3],
                        sb + aoff + ar * 256 + (ac << 4));
            }
            uint32_t bfr[2][4];
            #pragma unroll
            for (int nt2 = 0; nt2 < 2; nt2++) {
                int br = n_base + nt2 * 16 + ((quad >> 1) << 3) + l7;
                int bc = (2 * ks + (quad & 1)) ^ (br & 7);
                ldsm_x4(bfr[nt2][0], bfr[nt2][1], bfr[nt2][2], bfr[nt2][3],
                        sb + boff + br * 256 + (bc << 4));
            }
            #pragma unroll
            for (int mt = 0; mt < 4; mt++)
                #pragma unroll
                for (int nt = 0; nt < 4; nt++)
                    mma_bf16(acc[mt][nt], afr[mt], &bfr[nt >> 1][(nt & 1) * 2]);
        }
    }

    // ---- epilogue 1: normal-orientation writes ----
    int g = lane >> 2, tig = lane & 3;
    #pragma unroll
    for (int mt = 0; mt < 4; mt++) {
        int row0 = i0 + m_base + mt * 16 + g;
        #pragma unroll
        for (int nt = 0; nt < 4; nt++) {
            int col = j0 + n_base + nt * 8 + tig * 2;
            *(float2*)&g_sim[(size_t)row0 * NN + col] = make_float2(acc[mt][nt][0], acc[mt][nt][1]);
            *(float2*)&g_sim[(size_t)(row0 + 8) * NN + col] = make_float2(acc[mt][nt][2], acc[mt][nt][3]);
        }
    }

    // ---- epilogue 2: mirror via smem-staged transpose (off-diagonal only) ----
    if (bi != bj) {
        __syncthreads();                         // all warps done with operand smem
        float* sT = (float*)smem;                // [128 cols][stride 132] = 67.6 KB
        #pragma unroll
        for (int mt = 0; mt < 4; mt++) {
            int rl0 = m_base + mt * 16 + g;
            #pragma unroll
            for (int nt = 0; nt < 4; nt++) {
                int cl = n_base + nt * 8 + tig * 2;
                sT[(cl + 0) * 132 + rl0]     = acc[mt][nt][0];
                sT[(cl + 1) * 132 + rl0]     = acc[mt][nt][1];
                sT[(cl + 0) * 132 + rl0 + 8] = acc[mt][nt][2];
                sT[(cl + 1) * 132 + rl0 + 8] = acc[mt][nt][3];
            }
        }
        __syncthreads();
        #pragma unroll
        for (int it = 0; it < 16; it++) {
            int idx = it * 256 + tid;            // 4096 float4 groups
            int r = idx >> 5, c4 = idx & 31;
            float4 v = *(float4*)&sT[r * 132 + c4 * 4];
            *(float4*)&g_sim[(size_t)(j0 + r) * NN + i0 + c4 * 4] = v;
        }
    }
}

// ---------------- K2: slim per-row mining + fused finalize ----------------
// pass1: min_pos / max_neg / membership mask only. pass2 uses hoisted thresholds
// (nthr, pthr) and single-FMA softplus args. length_AP via class histogram.
__global__ void __launch_bounds__(256) k_rowpass(const int* __restrict__ tg,
                                                 const float* __restrict__ pm,
                                                 float* __restrict__ out) {
    __shared__ int   stg[NN];
    __shared__ float wr[8][5];
    __shared__ float fin[5];
    __shared__ int   s_is_last;
    __shared__ int   shist[64];

    int i = blockIdx.x;
    int tid = threadIdx.x;
    int lane = tid & 31, wid = tid >> 5;
    float margin = *pm;
    float m10 = margin / 10.0f;
    float m10f = floorf(m10);

    {
        const int4* tg4 = (const int4*)tg;
        int4* stg4 = (int4*)stg;
        for (int j = tid; j < NN / 4; j += 256) stg4[j] = tg4[j];
    }
    __syncthreads();
    int ti = stg[i];
    bool lastrow = (i == NN - 1);

    // ---- pass 1: load 16 elements into registers; min_pos / max_neg / same mask ----
    float sreg[16];
    uint32_t same_mask = 0;
    float minp = 1e9f, maxn = -1e9f;
    {
        const float4* row4 = (const float4*)&g_sim[(size_t)i * NN];
        const int4* stg4 = (const int4*)stg;
        #pragma unroll
        for (int v4 = 0; v4 < 4; v4++) {
            int j4 = v4 * 256 + tid;
            float4 s4 = row4[j4];
            int4 t4 = stg4[j4];
            float sv[4] = {s4.x, s4.y, s4.z, s4.w};
            int tv[4] = {t4.x, t4.y, t4.z, t4.w};
            #pragma unroll
            for (int u = 0; u < 4; u++) {
                int j = j4 * 4 + u;
                bool diag = (j == i);
                float s = diag ? 1.0f : sv[u];    // exact diagonal (unit-norm rows)
                sreg[v4 * 4 + u] = s;
                if (tv[u] == ti) {
                    same_mask |= (1u << (v4 * 4 + u));
                    if (!diag) minp = fminf(minp, s);
                } else {
                    maxn = fmaxf(maxn, s);
                }
            }
        }
    }
    float scnt = (float)__popc(same_mask);        // same-class count incl. diagonal

    // last-row CTA only: pre-mining sums (exact baseline order)
    float pps = 0.f, nns = 0.f;
    if (lastrow) {
        #pragma unroll
        for (int e = 0; e < 16; e++) {
            float s = sreg[e];
            if ((same_mask >> e) & 1) {
                if (s < 1.0f - C_EPS) pps += s;
            } else {
                nns += s;
            }
        }
    }

    float a = wmin(minp), b = wmax(maxn);
    float c0 = wsum(scnt), c1 = wsum(pps), c2 = wsum(nns);
    if (lane == 0) {
        wr[wid][0] = a; wr[wid][1] = b; wr[wid][2] = c0;
        wr[wid][3] = c1; wr[wid][4] = c2;
    }
    __syncthreads();
    if (tid == 0) {
        float v0 = 1e9f, v1 = -1e9f, v2 = 0.f, v3 = 0.f, v4 = 0.f;
        #pragma unroll
        for (int w = 0; w < 8; w++) {
            v0 = fminf(v0, wr[w][0]); v1 = fmaxf(v1, wr[w][1]);
            v2 += wr[w][2]; v3 += wr[w][3]; v4 += wr[w][4];
        }
        fin[0] = v0; fin[1] = v1; fin[2] = v2; fin[3] = v3; fin[4] = v4;
    }
    __syncthreads();

    // hoisted thresholds + folded softplus constants (per-CTA scalars)
    float nthr = fin[0] - m10;                         // neg sel: s > nthr
    float pthr = fminf(1.0f - C_EPS, fin[1] + margin); // pos sel: s < pthr
    float Cn = C_ALPHA * (m10 - m10f - C_BASE);        // neg arg = fma(10, s, Cn)
    float Cp = C_BETA * C_BASE;                        // pos arg = fma(-2, s, Cp)

    // ---- pass 2: mining + softplus sums (pure register math) ----
    float pc = 0.f, nc = 0.f, psum = 0.f, nsum = 0.f;
    #pragma unroll
    for (int e = 0; e < 16; e++) {
        float s = sreg[e];
        if ((same_mask >> e) & 1) {
            if (s < pthr) {
                pc += 1.0f;
                psum += __logf(1.0f + __expf(fmaf(-C_BETA, s, Cp)));
            }
        } else {
            if (s > nthr) {
                nc += 1.0f;
                nsum += __logf(1.0f + __expf(fmaf(C_ALPHA, s, Cn)));
            }
        }
    }
    float r0 = wsum(pc), r1 = wsum(nc), r2 = wsum(psum), r3 = wsum(nsum);
    __syncthreads();
    if (lane == 0) {
        wr[wid][0] = r0; wr[wid][1] = r1; wr[wid][2] = r2; wr[wid][3] = r3;
    }
    __syncthreads();
    if (tid == 0) {
        float v0 = 0.f, v1 = 0.f, v2 = 0.f, v3 = 0.f;
        #pragma unroll
        for (int w = 0; w < 8; w++) {
            v0 += wr[w][0]; v1 += wr[w][1]; v2 += wr[w][2]; v3 += wr[w][3];
        }
        g_rowpart[i * 4 + 0] = v0;
        g_rowpart[i * 4 + 1] = v1;
        g_rowpart[i * 4 + 2] = v2;
        g_rowpart[i * 4 + 3] = v3;
        if (lastrow) {
            g_last[0] = fin[3];                 // pre-mining pos sim sum
            g_last[1] = fin[2] - 1.0f;          // pos_mask count = |class| - 1
            g_last[2] = fin[4];                 // pre-mining neg sim sum
            g_last[3] = (float)NN - fin[2];     // neg count
        }
    }
    __syncthreads();

    // ---- last CTA finalizes ----
    if (tid == 0) {
        __threadfence();
        int done = atomicAdd(&g_ctr, 1);
        s_is_last = (done == NN - 1);
    }
    __syncthreads();
    if (!s_is_last) return;
    __threadfence();

    // class histogram from smem-resident targets -> length_AP = sum(cnt^2) - NN
    if (tid < 64) shist[tid] = 0;
    __syncthreads();
    for (int j = tid; j < NN; j += 256) atomicAdd(&shist[stg[j]], 1);
    __syncthreads();

    float lsum = 0.f, cinv = 0.f, lap = 0.f, lan = 0.f;
    for (int k = tid; k < NN; k += 256) {
        float cp = g_rowpart[k * 4 + 0];
        float cn = g_rowpart[k * 4 + 1];
        float ps = g_rowpart[k * 4 + 2];
        float ns = g_rowpart[k * 4 + 3];
        bool valid = (cp > 0.0f) && (cn > 0.0f);
        if (valid) {
            lsum += (2.0f / C_BETA) * ps / fmaxf(cp, 1.0f)
                  + (2.0f / C_ALPHA) * ns / fmaxf(cn, 1.0f);
            lap += cp;
            lan += cn;
        } else {
            cinv += 1.0f;
        }
    }
    lsum = wsum(lsum); cinv = wsum(cinv); lap = wsum(lap); lan = wsum(lan);
    __syncthreads();
    if (lane == 0) {
        wr[wid][0] = lsum; wr[wid][1] = cinv; wr[wid][2] = lap; wr[wid][3] = lan;
    }
    __syncthreads();
    if (tid == 0) {
        float v0 = 0.f, v1 = 0.f, v2 = 0.f, v3 = 0.f;
        #pragma unroll
        for (int w = 0; w < 8; w++) {
            v0 += wr[w][0]; v1 += wr[w][1]; v2 += wr[w][2]; v3 += wr[w][3];
        }
        long long sum2 = 0;
        #pragma unroll
        for (int c = 0; c < 64; c++) {
            long long h = shist[c];
            sum2 += h * h;
        }
        float lAP = (float)(sum2 - NN);

        float nf = (float)NN;
        float loss = v0 / nf;
        float prec = v1 / nf;
        float mps = g_last[0] / fmaxf(g_last[1], 1.0f);
        float mns = g_last[2] / fmaxf(g_last[3], 1.0f);
        float la = v2 * 0.5f;
        float ln_ = v3 * 0.5f;
        float rr1 = ln_ / la;
        float s1 = 1.0f / (1.0f + __expf(-rr1));
        float rr2 = ln_ / (lAP * 0.5f);
        float s2 = 1.0f / (1.0f + __expf(-rr2));
        out[0] = loss; out[1] = prec; out[2] = mps; out[3] = mns;
        out[4] = la;   out[5] = ln_;  out[6] = rr1; out[7] = s1;
        out[8] = rr2;  out[9] = s2;
    }
}

// ---------------- host launcher ----------------
extern "C" void kernel_launch(void* const* d_in, const int* in_sizes, int n_in,
                              void* d_out, int out_size) {
    const float* X       = (const float*)d_in[0];
    const int*   targets = (const int*)d_in[1];
    const float* margin  = (const float*)d_in[2];
    float* out = (float*)d_out;

    k_convert<<<(NN * DD / 4) / 256, 256>>>(X);

    cudaFuncSetAttribute(k_gemm_mma, cudaFuncAttributeMaxDynamicSharedMemorySize, 4 * TILE_B);
    k_gemm_mma<<<528, 256, 4 * TILE_B>>>();

    k_rowpass<<<NN, 256>>>(targets, margin, out);
}